// round 8
// baseline (speedup 1.0000x reference)
#include <cuda_runtime.h>

#define TILE_B   4
#define THREADS  256
#define NB       8192
#define NIO      64
#define SETUP_BLOCKS 16

// Precomputed per-(o,i) coefficient tables, laid out [i][o] for coalesced
// per-o lane reads.  A = {c1', b2', b3', b4}, B = {c5..c8} (gamma/64 folded).
__device__ float4 g_tabA[NIO * NIO];
__device__ float4 g_tabB[NIO * NIO];
__device__ unsigned g_done = 0;   // monotonic arrival counter (replay-safe)

__device__ __forceinline__ float ex2f_(float x) {
    float y; asm("ex2.approx.ftz.f32 %0, %1;" : "=f"(y) : "f"(x)); return y;
}
__device__ __forceinline__ float lg2f_(float x) {
    float y; asm("lg2.approx.ftz.f32 %0, %1;" : "=f"(y) : "f"(x)); return y;
}

// ---------------------------------------------------------------------------
// Per-pair table setup (one (o,i) pair per thread).  Runs as a prologue on
// blocks 0..15.  __noinline__ keeps its register use out of the main loop's
// allocation.
// ---------------------------------------------------------------------------
__device__ __noinline__ void setup_pair(int tid,
                                        const float* __restrict__ raw_gamma,
                                        const float* __restrict__ w,
                                        const float* __restrict__ breaks,
                                        const float* __restrict__ coefs,
                                        const float* __restrict__ mu_p,
                                        const float* __restrict__ sig_p)
{
    int o = tid >> 6;
    int i = tid & 63;

    float mu  = *mu_p;
    float sig = *sig_p;
    float wv  = __ldg(&w[tid]);               // w[o][i]
    float wc  = fminf(fmaxf(wv, -5.5f), 37.9f);
    float wn  = (wc - mu) / sig;

    float b[8];
#pragma unroll
    for (int s = 0; s < 8; s++) {
        const float* br = breaks + s * 20;
        float blo = __ldg(&br[0]);
        float bhi = __ldg(&br[19]) - 1e-6f;
        float wl  = fminf(fmaxf(wn, blo), bhi);
        int cnt = 0;
#pragma unroll
        for (int k = 0; k < 20; k++) cnt += (__ldg(&br[k]) < wl) ? 1 : 0;
        int idx = cnt - 1;
        idx = max(idx, 0);
        idx = min(idx, 18);
        const float* a = coefs + (s * 19 + idx) * 4;
        float t = wl - __ldg(&br[idx]);
        b[s] = ((__ldg(&a[0]) * t + __ldg(&a[1])) * t + __ldg(&a[2])) * t + __ldg(&a[3]);
    }

    float rg = __ldg(&raw_gamma[tid]);
    float g  = (rg > 20.f) ? rg : log1pf(expf(rg));   // softplus
    float scale = g * (1.0f / 64.0f);

    const float LN2   = 0.6931471805599453f;
    const float LOG2E = 1.4426950408889634f;

    float4 A, Bq;
    A.x = b[0] * scale * LN2;   // c1'
    A.y = b[1] * LN2;           // b2'
    A.z = b[2] * LOG2E;         // b3'
    A.w = b[3];                 // b4
    Bq.x = b[4] * scale;
    Bq.y = b[5] * scale;
    Bq.z = b[6] * scale;
    Bq.w = b[7] * scale;

    int p = i * NIO + o;        // [i][o] layout
    g_tabA[p] = A;
    g_tabB[p] = Bq;
}

// ---------------------------------------------------------------------------
// Fused kernel.  Block = 256 threads = 8 warps, TILE_B=4 rows, grid=2048.
// Blocks 0..15 first compute the 64x64 coefficient tables (256 pairs each),
// publish via threadfence + monotonic counter; every block spins (thread 0)
// until all 16 slices are published.  Replays pass the spin instantly and
// rewrite identical table bytes (benign, deterministic).
//
// Main loop: warp wp -> row (wp>>1), o-half (wp&1).  Two 32-bit activity
// masks drained together (2 independent MUFU chains); xv+A software-
// pipelined one step ahead, B loaded inside the chain (its poly consumers
// sit ~80 cycles in, so the L1-hit latency is free).
// ---------------------------------------------------------------------------
__global__ __launch_bounds__(THREADS, 5)
void fused_kernel(const float* __restrict__ x, float* __restrict__ out,
                  const float* __restrict__ raw_gamma,
                  const float* __restrict__ w,
                  const float* __restrict__ breaks,
                  const float* __restrict__ coefs,
                  const float* __restrict__ mu_p,
                  const float* __restrict__ sig_p)
{
    __shared__ float xs[TILE_B * 64];

    const int tid   = threadIdx.x;
    const long base = (long)blockIdx.x * (TILE_B * 64);

    // Phase 0: load x tile + relu (independent of tables)
    xs[tid] = fmaxf(x[base + tid], 0.f);

    // Table setup prologue on the first 16 blocks
    if (blockIdx.x < SETUP_BLOCKS) {
        setup_pair(blockIdx.x * THREADS + tid,
                   raw_gamma, w, breaks, coefs, mu_p, sig_p);
        __threadfence();
        __syncthreads();
        if (tid == 0) atomicAdd(&g_done, 1u);
    }

    // Wait until all 16 table slices are published (instant on replays)
    if (tid == 0) {
        while (*(volatile unsigned*)&g_done < SETUP_BLOCKS) __nanosleep(64);
    }
    __syncthreads();
    __threadfence();

    const int lane = tid & 31;
    const int wp   = tid >> 5;
    const int r    = wp >> 1;
    const int o    = lane + (wp & 1) * 32;

    const float* xrow = xs + r * 64;
    float v0 = xrow[lane];
    float v1 = xrow[lane + 32];
    unsigned lo = __ballot_sync(0xffffffffu, v0 > 0.f);
    unsigned hi = __ballot_sync(0xffffffffu, v1 > 0.f);

    const float4* tA = g_tabA + o;
    const float4* tB = g_tabB + o;

    float acc0 = 0.f, acc1 = 0.f;

    // COMPUTE on prefetched xv/A; B loaded here (hidden under the MUFU chain)
#define CHAIN(ACC, XV, A, II)                                             \
    {                                                                     \
        float4 Bq = __ldg(tB + (II) * NIO);                               \
        float e  = ex2f_((A).z * (XV)) - 1.f;                             \
        float p  = ex2f_((A).w * lg2f_(e));                               \
        float l1 = lg2f_(1.f + p);                                        \
        float l2 = lg2f_(fmaf((A).y, l1, 1.f));                           \
        ACC = fmaf((A).x, l2, ACC);                                       \
        float x2 = (XV) * (XV);                                           \
        float pA = fmaf(Bq.z, x2, Bq.x);                                  \
        float pB = fmaf(Bq.w, x2, Bq.y);                                  \
        ACC = fmaf(fmaf(pB, (XV), pA), (XV), ACC);                        \
    }

    int nb = min(__popc(lo), __popc(hi));

    if (nb > 0) {
        // Prologue: fetch step 0 for both chains
        int i0 = __ffs(lo) - 1;  lo &= lo - 1;
        int i1 = __ffs(hi) + 31; hi &= hi - 1;
        float  xv0 = xrow[i0];
        float  xv1 = xrow[i1];
        float4 A0  = __ldg(tA + i0 * NIO);
        float4 A1  = __ldg(tA + i1 * NIO);
        int ci0 = i0, ci1 = i1;

        for (int k = 1; k < nb; k++) {
            // FETCH next step
            int j0 = __ffs(lo) - 1;  lo &= lo - 1;
            int j1 = __ffs(hi) + 31; hi &= hi - 1;
            float  nxv0 = xrow[j0];
            float  nxv1 = xrow[j1];
            float4 nA0  = __ldg(tA + j0 * NIO);
            float4 nA1  = __ldg(tA + j1 * NIO);

            // COMPUTE current step (2 independent MUFU chains)
            CHAIN(acc0, xv0, A0, ci0);
            CHAIN(acc1, xv1, A1, ci1);

            // rotate
            xv0 = nxv0; A0 = nA0; ci0 = j0;
            xv1 = nxv1; A1 = nA1; ci1 = j1;
        }
        // Epilogue
        CHAIN(acc0, xv0, A0, ci0);
        CHAIN(acc1, xv1, A1, ci1);
    }

    // Remainder drains (one mask already empty; counts are small)
    while (lo) {
        int i0 = __ffs(lo) - 1; lo &= lo - 1;
        float  xv = xrow[i0];
        float4 A  = __ldg(tA + i0 * NIO);
        CHAIN(acc0, xv, A, i0);
    }
    while (hi) {
        int i1 = __ffs(hi) + 31; hi &= hi - 1;
        float  xv = xrow[i1];
        float4 A  = __ldg(tA + i1 * NIO);
        CHAIN(acc1, xv, A, i1);
    }
#undef CHAIN

    out[base + r * 64 + o] = acc0 + acc1;
}

// ---------------------------------------------------------------------------
extern "C" void kernel_launch(void* const* d_in, const int* in_sizes, int n_in,
                              void* d_out, int out_size)
{
    const float* x   = (const float*)d_in[0];
    const float* rg  = (const float*)d_in[1];
    const float* w   = (const float*)d_in[2];
    const float* br  = (const float*)d_in[3];
    const float* cf  = (const float*)d_in[4];
    const float* mu  = (const float*)d_in[5];
    const float* sg  = (const float*)d_in[6];
    float* out = (float*)d_out;

    fused_kernel<<<NB / TILE_B, THREADS>>>(x, out, rg, w, br, cf, mu, sg);
}

// round 9
// speedup vs baseline: 1.4139x; 1.4139x over previous
#include <cuda_runtime.h>

#define TILE_B   4
#define THREADS  128
#define NB       8192
#define NIO      64

// Precomputed per-(o,i) coefficient tables, laid out [i][o] for coalesced
// per-o lane reads.  A = {c1', b2', b3', b4}, B = {c5..c8} (gamma/64 folded).
__device__ float4 g_tabA[NIO * NIO];
__device__ float4 g_tabB[NIO * NIO];

__device__ __forceinline__ float ex2f_(float x) {
    float y; asm("ex2.approx.ftz.f32 %0, %1;" : "=f"(y) : "f"(x)); return y;
}
__device__ __forceinline__ float lg2f_(float x) {
    float y; asm("lg2.approx.ftz.f32 %0, %1;" : "=f"(y) : "f"(x)); return y;
}

// ---------------------------------------------------------------------------
// Setup: evaluate the 8 cubic splines at w_norm for every (o,i) pair and fold
// all constant factors so the main loop is pure EX2/LG2 + FFMA.
// breaks/coefs staged through smem.
// ---------------------------------------------------------------------------
__global__ void setup_kernel(const float* __restrict__ raw_gamma,
                             const float* __restrict__ w,
                             const float* __restrict__ breaks,
                             const float* __restrict__ coefs,
                             const float* __restrict__ mu_p,
                             const float* __restrict__ sig_p)
{
    __shared__ float sbr[8 * 20];
    __shared__ float scf[8 * 19 * 4];

    int t = threadIdx.x;
    if (t < 160) sbr[t] = breaks[t];
    for (int k = t; k < 8 * 19 * 4; k += blockDim.x) scf[k] = coefs[k];
    __syncthreads();

    int tid = blockIdx.x * blockDim.x + t;
    if (tid >= NIO * NIO) return;
    int o = tid >> 6;
    int i = tid & 63;

    float mu  = *mu_p;
    float sig = *sig_p;
    float wv  = w[tid];                       // w[o][i]
    float wc  = fminf(fmaxf(wv, -5.5f), 37.9f);
    float wn  = (wc - mu) / sig;

    float b[8];
#pragma unroll
    for (int s = 0; s < 8; s++) {
        const float* br = sbr + s * 20;
        float blo = br[0];
        float bhi = br[19] - 1e-6f;
        float wl  = fminf(fmaxf(wn, blo), bhi);
        int cnt = 0;
#pragma unroll
        for (int k = 0; k < 20; k++) cnt += (br[k] < wl) ? 1 : 0;
        int idx = cnt - 1;
        idx = max(idx, 0);
        idx = min(idx, 18);
        const float* a = scf + (s * 19 + idx) * 4;
        float tt = wl - br[idx];
        b[s] = ((a[0] * tt + a[1]) * tt + a[2]) * tt + a[3];
    }

    float rg = raw_gamma[tid];
    float g  = (rg > 20.f) ? rg : log1pf(expf(rg));   // softplus
    float scale = g * (1.0f / 64.0f);

    const float LN2   = 0.6931471805599453f;
    const float LOG2E = 1.4426950408889634f;

    float4 A, Bq;
    A.x = b[0] * scale * LN2;   // c1'
    A.y = b[1] * LN2;           // b2'
    A.z = b[2] * LOG2E;         // b3'
    A.w = b[3];                 // b4
    Bq.x = b[4] * scale;
    Bq.y = b[5] * scale;
    Bq.z = b[6] * scale;
    Bq.w = b[7] * scale;

    int p = i * NIO + o;        // [i][o] layout
    g_tabA[p] = A;
    g_tabB[p] = Bq;
}

// ---------------------------------------------------------------------------
// Main kernel.  Block = 128 threads = 4 warps, TILE_B=4 rows, grid=2048.
// ONE WARP PER ROW: lane handles outputs o=lane and o+32.  Each step drains
// one active index i from a 64-bit mask (single-end ffsll) and runs TWO
// independent MUFU chains (outputs o, o+32) sharing xv/i — balanced by
// construction, no remainder loops, half the control overhead per chain.
// Software pipelined: xv + A0/A1 fetched one step ahead; B loaded inside
// the chain (consumers ~80 cycles in, L1-hit latency fully hidden).
// ---------------------------------------------------------------------------
__global__ __launch_bounds__(THREADS)
void main_kernel(const float* __restrict__ x, float* __restrict__ out)
{
    __shared__ float xs[TILE_B * 64];

    const int tid   = threadIdx.x;
    const long base = (long)blockIdx.x * (TILE_B * 64);

    // Phase 1: load x tile + relu (coalesced)
    xs[tid]       = fmaxf(x[base + tid], 0.f);
    xs[tid + 128] = fmaxf(x[base + tid + 128], 0.f);
    __syncthreads();

    const int lane = tid & 31;
    const int wp   = tid >> 5;
    const int r    = wp;
    const int o    = lane;

    const float* xrow = xs + r * 64;
    float v0 = xrow[lane];
    float v1 = xrow[lane + 32];
    unsigned lo = __ballot_sync(0xffffffffu, v0 > 0.f);
    unsigned hi = __ballot_sync(0xffffffffu, v1 > 0.f);
    unsigned long long m = (unsigned long long)lo |
                           ((unsigned long long)hi << 32);

    const float4* tA0 = g_tabA + o;
    const float4* tA1 = g_tabA + o + 32;
    const float4* tB0 = g_tabB + o;
    const float4* tB1 = g_tabB + o + 32;

    float acc0 = 0.f, acc1 = 0.f;

    // Two chains sharing XV/index; B loaded here (hidden under MUFU chain)
#define STEP2(II, XV, A0, A1)                                             \
    {                                                                     \
        float4 B0 = __ldg(tB0 + (II) * NIO);                              \
        float4 B1 = __ldg(tB1 + (II) * NIO);                              \
        float x2 = (XV) * (XV);                                           \
        float e0  = ex2f_((A0).z * (XV)) - 1.f;                           \
        float e1  = ex2f_((A1).z * (XV)) - 1.f;                           \
        float p0  = ex2f_((A0).w * lg2f_(e0));                            \
        float p1  = ex2f_((A1).w * lg2f_(e1));                            \
        float l10 = lg2f_(1.f + p0);                                      \
        float l11 = lg2f_(1.f + p1);                                      \
        float l20 = lg2f_(fmaf((A0).y, l10, 1.f));                        \
        float l21 = lg2f_(fmaf((A1).y, l11, 1.f));                        \
        acc0 = fmaf((A0).x, l20, acc0);                                   \
        acc1 = fmaf((A1).x, l21, acc1);                                   \
        float pA0 = fmaf(B0.z, x2, B0.x);                                 \
        float pB0 = fmaf(B0.w, x2, B0.y);                                 \
        float pA1 = fmaf(B1.z, x2, B1.x);                                 \
        float pB1 = fmaf(B1.w, x2, B1.y);                                 \
        acc0 = fmaf(fmaf(pB0, (XV), pA0), (XV), acc0);                    \
        acc1 = fmaf(fmaf(pB1, (XV), pA1), (XV), acc1);                    \
    }

    int nb = __popcll(m);

    if (nb > 0) {
        // Prologue: fetch step 0
        int ci = __ffsll(m) - 1;  m &= m - 1;
        float  xv = xrow[ci];
        float4 A0 = __ldg(tA0 + ci * NIO);
        float4 A1 = __ldg(tA1 + ci * NIO);

        for (int k = 1; k < nb; k++) {
            // FETCH next step
            int j = __ffsll(m) - 1;  m &= m - 1;
            float  nxv = xrow[j];
            float4 nA0 = __ldg(tA0 + j * NIO);
            float4 nA1 = __ldg(tA1 + j * NIO);

            // COMPUTE current step (2 independent MUFU chains)
            STEP2(ci, xv, A0, A1);

            // rotate
            ci = j; xv = nxv; A0 = nA0; A1 = nA1;
        }
        // Epilogue
        STEP2(ci, xv, A0, A1);
    }
#undef STEP2

    out[base + r * 64 + o]      = acc0;
    out[base + r * 64 + o + 32] = acc1;
}

// ---------------------------------------------------------------------------
extern "C" void kernel_launch(void* const* d_in, const int* in_sizes, int n_in,
                              void* d_out, int out_size)
{
    const float* x   = (const float*)d_in[0];
    const float* rg  = (const float*)d_in[1];
    const float* w   = (const float*)d_in[2];
    const float* br  = (const float*)d_in[3];
    const float* cf  = (const float*)d_in[4];
    const float* mu  = (const float*)d_in[5];
    const float* sg  = (const float*)d_in[6];
    float* out = (float*)d_out;

    setup_kernel<<<(NIO * NIO + 255) / 256, 256>>>(rg, w, br, cf, mu, sg);
    main_kernel<<<NB / TILE_B, THREADS>>>(x, out);
}

// round 10
// speedup vs baseline: 1.4154x; 1.0010x over previous
#include <cuda_runtime.h>

#define TILE_B   4
#define THREADS  128
#define NB       8192
#define NIO      64

// Precomputed per-(o,i) coefficient tables, laid out [i][o] for coalesced
// per-o lane reads.  A = {c1', b2', b3', b4}, B = {c5..c8} (gamma/64 folded).
__device__ float4 g_tabA[NIO * NIO];
__device__ float4 g_tabB[NIO * NIO];

__device__ __forceinline__ float ex2f_(float x) {
    float y; asm("ex2.approx.ftz.f32 %0, %1;" : "=f"(y) : "f"(x)); return y;
}
__device__ __forceinline__ float lg2f_(float x) {
    float y; asm("lg2.approx.ftz.f32 %0, %1;" : "=f"(y) : "f"(x)); return y;
}

// ---------------------------------------------------------------------------
// Setup: evaluate the 8 cubic splines at w_norm for every (o,i) pair and fold
// all constant factors so the main loop is pure EX2/LG2 + FFMA.
// breaks/coefs staged through smem.
// ---------------------------------------------------------------------------
__global__ void setup_kernel(const float* __restrict__ raw_gamma,
                             const float* __restrict__ w,
                             const float* __restrict__ breaks,
                             const float* __restrict__ coefs,
                             const float* __restrict__ mu_p,
                             const float* __restrict__ sig_p)
{
    __shared__ float sbr[8 * 20];
    __shared__ float scf[8 * 19 * 4];

    int t = threadIdx.x;
    if (t < 160) sbr[t] = breaks[t];
    for (int k = t; k < 8 * 19 * 4; k += blockDim.x) scf[k] = coefs[k];
    __syncthreads();

    int tid = blockIdx.x * blockDim.x + t;
    if (tid >= NIO * NIO) return;
    int o = tid >> 6;
    int i = tid & 63;

    float mu  = *mu_p;
    float sig = *sig_p;
    float wv  = w[tid];                       // w[o][i]
    float wc  = fminf(fmaxf(wv, -5.5f), 37.9f);
    float wn  = (wc - mu) / sig;

    float b[8];
#pragma unroll
    for (int s = 0; s < 8; s++) {
        const float* br = sbr + s * 20;
        float blo = br[0];
        float bhi = br[19] - 1e-6f;
        float wl  = fminf(fmaxf(wn, blo), bhi);
        int cnt = 0;
#pragma unroll
        for (int k = 0; k < 20; k++) cnt += (br[k] < wl) ? 1 : 0;
        int idx = cnt - 1;
        idx = max(idx, 0);
        idx = min(idx, 18);
        const float* a = scf + (s * 19 + idx) * 4;
        float tt = wl - br[idx];
        b[s] = ((a[0] * tt + a[1]) * tt + a[2]) * tt + a[3];
    }

    float rg = raw_gamma[tid];
    float g  = (rg > 20.f) ? rg : log1pf(expf(rg));   // softplus
    float scale = g * (1.0f / 64.0f);

    const float LN2   = 0.6931471805599453f;
    const float LOG2E = 1.4426950408889634f;

    float4 A, Bq;
    A.x = b[0] * scale * LN2;   // c1'
    A.y = b[1] * LN2;           // b2'
    A.z = b[2] * LOG2E;         // b3'
    A.w = b[3];                 // b4
    Bq.x = b[4] * scale;
    Bq.y = b[5] * scale;
    Bq.z = b[6] * scale;
    Bq.w = b[7] * scale;

    int p = i * NIO + o;        // [i][o] layout
    g_tabA[p] = A;
    g_tabB[p] = Bq;
}

// ---------------------------------------------------------------------------
// Main kernel.  Block = 128 threads = 4 warps, TILE_B=4 rows, grid=2048.
// ONE WARP PER ROW, warp-private: each warp relu-loads its row, compacts the
// active (x>0) entries ONCE into parallel smem arrays xc[] (value) + ic[]
// (index) via ballot/popc-prefix, then runs a COUNTED loop: per step one
// LDS.32 + one LDS.U8 (independent, prefetched one ahead) feed two MUFU
// chains (outputs o=lane, o+32) sharing xv.  No per-step mask arithmetic,
// no block barriers.  B-table loads sit inside the chain (latency hidden).
// ---------------------------------------------------------------------------
__global__ __launch_bounds__(THREADS)
void main_kernel(const float* __restrict__ x, float* __restrict__ out)
{
    __shared__ float         xc[TILE_B * 64];   // compacted x values per row
    __shared__ unsigned char ic[TILE_B * 64];   // compacted indices per row

    const int tid   = threadIdx.x;
    const long base = (long)blockIdx.x * (TILE_B * 64);

    const int lane = tid & 31;
    const int wp   = tid >> 5;
    const int r    = wp;
    const int o    = lane;

    // Phase 1 (warp-private): load row, relu, compact actives into xc/ic.
    float v0 = fmaxf(x[base + r * 64 + lane], 0.f);
    float v1 = fmaxf(x[base + r * 64 + 32 + lane], 0.f);
    unsigned lo = __ballot_sync(0xffffffffu, v0 > 0.f);
    unsigned hi = __ballot_sync(0xffffffffu, v1 > 0.f);
    const unsigned lmask_lt = (lane == 0) ? 0u : (0xffffffffu >> (32 - lane));
    int cnt0 = __popc(lo);
    int cnt  = cnt0 + __popc(hi);

    float*         xrow = xc + r * 64;
    unsigned char* irow = ic + r * 64;
    if (v0 > 0.f) {
        int p = __popc(lo & lmask_lt);
        xrow[p] = v0; irow[p] = (unsigned char)lane;
    }
    if (v1 > 0.f) {
        int p = cnt0 + __popc(hi & lmask_lt);
        xrow[p] = v1; irow[p] = (unsigned char)(lane + 32);
    }
    __syncwarp();

    const float4* tA0 = g_tabA + o;
    const float4* tA1 = g_tabA + o + 32;
    const float4* tB0 = g_tabB + o;
    const float4* tB1 = g_tabB + o + 32;

    float acc0 = 0.f, acc1 = 0.f;

    // Two chains sharing XV; B loaded here (hidden under the MUFU chain)
#define STEP2(II, XV, A0, A1)                                             \
    {                                                                     \
        float4 B0 = __ldg(tB0 + (II) * NIO);                              \
        float4 B1 = __ldg(tB1 + (II) * NIO);                              \
        float x2 = (XV) * (XV);                                           \
        float e0  = ex2f_((A0).z * (XV)) - 1.f;                           \
        float e1  = ex2f_((A1).z * (XV)) - 1.f;                           \
        float p0  = ex2f_((A0).w * lg2f_(e0));                            \
        float p1  = ex2f_((A1).w * lg2f_(e1));                            \
        float l10 = lg2f_(1.f + p0);                                      \
        float l11 = lg2f_(1.f + p1);                                      \
        float l20 = lg2f_(fmaf((A0).y, l10, 1.f));                        \
        float l21 = lg2f_(fmaf((A1).y, l11, 1.f));                        \
        acc0 = fmaf((A0).x, l20, acc0);                                   \
        acc1 = fmaf((A1).x, l21, acc1);                                   \
        float pA0 = fmaf(B0.z, x2, B0.x);                                 \
        float pB0 = fmaf(B0.w, x2, B0.y);                                 \
        float pA1 = fmaf(B1.z, x2, B1.x);                                 \
        float pB1 = fmaf(B1.w, x2, B1.y);                                 \
        acc0 = fmaf(fmaf(pB0, (XV), pA0), (XV), acc0);                    \
        acc1 = fmaf(fmaf(pB1, (XV), pA1), (XV), acc1);                    \
    }

    if (cnt > 0) {
        // Prologue: fetch step 0
        int    ci = irow[0];
        float  xv = xrow[0];
        float4 A0 = __ldg(tA0 + ci * NIO);
        float4 A1 = __ldg(tA1 + ci * NIO);

        for (int k = 1; k < cnt; k++) {
            // FETCH next step (xc and ic loads are independent)
            int    nj  = irow[k];
            float  nxv = xrow[k];
            float4 nA0 = __ldg(tA0 + nj * NIO);
            float4 nA1 = __ldg(tA1 + nj * NIO);

            // COMPUTE current step (2 independent MUFU chains)
            STEP2(ci, xv, A0, A1);

            // rotate
            ci = nj; xv = nxv; A0 = nA0; A1 = nA1;
        }
        // Epilogue
        STEP2(ci, xv, A0, A1);
    }
#undef STEP2

    out[base + r * 64 + o]      = acc0;
    out[base + r * 64 + o + 32] = acc1;
}

// ---------------------------------------------------------------------------
extern "C" void kernel_launch(void* const* d_in, const int* in_sizes, int n_in,
                              void* d_out, int out_size)
{
    const float* x   = (const float*)d_in[0];
    const float* rg  = (const float*)d_in[1];
    const float* w   = (const float*)d_in[2];
    const float* br  = (const float*)d_in[3];
    const float* cf  = (const float*)d_in[4];
    const float* mu  = (const float*)d_in[5];
    const float* sg  = (const float*)d_in[6];
    float* out = (float*)d_out;

    setup_kernel<<<(NIO * NIO + 255) / 256, 256>>>(rg, w, br, cf, mu, sg);
    main_kernel<<<NB / TILE_B, THREADS>>>(x, out);
}

// round 11
// speedup vs baseline: 1.5132x; 1.0691x over previous
#include <cuda_runtime.h>

#define TILE_B   4
#define THREADS  128
#define NB       8192
#define NIO      64

// Precomputed per-(o,i) coefficient tables, laid out [i][o] for coalesced
// per-o lane reads.  A = {c1', b2', b3', b4}, B = {c5..c8} (gamma/64 folded).
__device__ float4 g_tabA[NIO * NIO];
__device__ float4 g_tabB[NIO * NIO];

__device__ __forceinline__ float ex2f_(float x) {
    float y; asm("ex2.approx.ftz.f32 %0, %1;" : "=f"(y) : "f"(x)); return y;
}
__device__ __forceinline__ float lg2f_(float x) {
    float y; asm("lg2.approx.ftz.f32 %0, %1;" : "=f"(y) : "f"(x)); return y;
}

// ---------------------------------------------------------------------------
// Setup: evaluate the 8 cubic splines at w_norm for every (o,i) pair and fold
// all constant factors so the main loop is pure EX2/LG2 + FFMA.
// Signals dependent-launch readiness at the end (PDL).
// ---------------------------------------------------------------------------
__global__ void setup_kernel(const float* __restrict__ raw_gamma,
                             const float* __restrict__ w,
                             const float* __restrict__ breaks,
                             const float* __restrict__ coefs,
                             const float* __restrict__ mu_p,
                             const float* __restrict__ sig_p)
{
    __shared__ float sbr[8 * 20];
    __shared__ float scf[8 * 19 * 4];

    int t = threadIdx.x;
    if (t < 160) sbr[t] = breaks[t];
    for (int k = t; k < 8 * 19 * 4; k += blockDim.x) scf[k] = coefs[k];
    __syncthreads();

    int tid = blockIdx.x * blockDim.x + t;
    if (tid < NIO * NIO) {
        int o = tid >> 6;
        int i = tid & 63;

        float mu  = *mu_p;
        float sig = *sig_p;
        float wv  = w[tid];                       // w[o][i]
        float wc  = fminf(fmaxf(wv, -5.5f), 37.9f);
        float wn  = (wc - mu) / sig;

        float b[8];
#pragma unroll
        for (int s = 0; s < 8; s++) {
            const float* br = sbr + s * 20;
            float blo = br[0];
            float bhi = br[19] - 1e-6f;
            float wl  = fminf(fmaxf(wn, blo), bhi);
            int cnt = 0;
#pragma unroll
            for (int k = 0; k < 20; k++) cnt += (br[k] < wl) ? 1 : 0;
            int idx = cnt - 1;
            idx = max(idx, 0);
            idx = min(idx, 18);
            const float* a = scf + (s * 19 + idx) * 4;
            float tt = wl - br[idx];
            b[s] = ((a[0] * tt + a[1]) * tt + a[2]) * tt + a[3];
        }

        float rg = raw_gamma[tid];
        float g  = (rg > 20.f) ? rg : log1pf(expf(rg));   // softplus
        float scale = g * (1.0f / 64.0f);

        const float LN2   = 0.6931471805599453f;
        const float LOG2E = 1.4426950408889634f;

        float4 A, Bq;
        A.x = b[0] * scale * LN2;   // c1'
        A.y = b[1] * LN2;           // b2'
        A.z = b[2] * LOG2E;         // b3'
        A.w = b[3];                 // b4
        Bq.x = b[4] * scale;
        Bq.y = b[5] * scale;
        Bq.z = b[6] * scale;
        Bq.w = b[7] * scale;

        int p = i * NIO + o;        // [i][o] layout
        g_tabA[p] = A;
        g_tabB[p] = Bq;
    }

    // Allow the dependent (main) grid to launch; its griddepcontrol.wait
    // releases only when this kernel fully completes (writes visible).
    asm volatile("griddepcontrol.launch_dependents;");
}

// ---------------------------------------------------------------------------
// Main kernel.  Block = 128 threads = 4 warps, TILE_B=4 rows, grid=2048.
// ONE WARP PER ROW: warp compacts its row's active entries once into parallel
// smem arrays xc/ic, then a counted loop processes TWO steps per iteration
// (pair-prefetched) = FOUR interleaved MUFU chains per warp, doubling
// per-warp MUFU supply (0.25/cyc vs the 0.125/cyc SMSP rate).
// Launched with PDL: phase 1 (x load + compaction) runs concurrently with
// setup_kernel; griddepcontrol.wait gates only the table reads.
// ---------------------------------------------------------------------------
__global__ __launch_bounds__(THREADS)
void main_kernel(const float* __restrict__ x, float* __restrict__ out)
{
    __shared__ float         xc[TILE_B * 64];   // compacted x values per row
    __shared__ unsigned char ic[TILE_B * 64];   // compacted indices per row

    const int tid   = threadIdx.x;
    const long base = (long)blockIdx.x * (TILE_B * 64);

    const int lane = tid & 31;
    const int wp   = tid >> 5;
    const int r    = wp;
    const int o    = lane;

    // Phase 1 (warp-private, table-independent): load row, relu, compact.
    float v0 = fmaxf(x[base + r * 64 + lane], 0.f);
    float v1 = fmaxf(x[base + r * 64 + 32 + lane], 0.f);
    unsigned lo = __ballot_sync(0xffffffffu, v0 > 0.f);
    unsigned hi = __ballot_sync(0xffffffffu, v1 > 0.f);
    const unsigned lmask_lt = (lane == 0) ? 0u : (0xffffffffu >> (32 - lane));
    int cnt0 = __popc(lo);
    int cnt  = cnt0 + __popc(hi);

    float*         xrow = xc + r * 64;
    unsigned char* irow = ic + r * 64;
    if (v0 > 0.f) {
        int p = __popc(lo & lmask_lt);
        xrow[p] = v0; irow[p] = (unsigned char)lane;
    }
    if (v1 > 0.f) {
        int p = cnt0 + __popc(hi & lmask_lt);
        xrow[p] = v1; irow[p] = (unsigned char)(lane + 32);
    }
    __syncwarp();

    // Gate on setup_kernel completion (PDL).  No-op when not PDL-launched.
    asm volatile("griddepcontrol.wait;");

    const float4* tA0 = g_tabA + o;
    const float4* tA1 = g_tabA + o + 32;
    const float4* tB0 = g_tabB + o;
    const float4* tB1 = g_tabB + o + 32;

    float acc0 = 0.f, acc1 = 0.f;

    // Two chains sharing XV; B loaded here (hidden under the MUFU chain)
#define STEP2(II, XV, A0, A1)                                             \
    {                                                                     \
        float4 B0 = __ldg(tB0 + (II) * NIO);                              \
        float4 B1 = __ldg(tB1 + (II) * NIO);                              \
        float x2 = (XV) * (XV);                                           \
        float e0  = ex2f_((A0).z * (XV)) - 1.f;                           \
        float e1  = ex2f_((A1).z * (XV)) - 1.f;                           \
        float p0  = ex2f_((A0).w * lg2f_(e0));                            \
        float p1  = ex2f_((A1).w * lg2f_(e1));                            \
        float l10 = lg2f_(1.f + p0);                                      \
        float l11 = lg2f_(1.f + p1);                                      \
        float l20 = lg2f_(fmaf((A0).y, l10, 1.f));                        \
        float l21 = lg2f_(fmaf((A1).y, l11, 1.f));                        \
        acc0 = fmaf((A0).x, l20, acc0);                                   \
        acc1 = fmaf((A1).x, l21, acc1);                                   \
        float pA0 = fmaf(B0.z, x2, B0.x);                                 \
        float pB0 = fmaf(B0.w, x2, B0.y);                                 \
        float pA1 = fmaf(B1.z, x2, B1.x);                                 \
        float pB1 = fmaf(B1.w, x2, B1.y);                                 \
        acc0 = fmaf(fmaf(pB0, (XV), pA0), (XV), acc0);                    \
        acc1 = fmaf(fmaf(pB1, (XV), pA1), (XV), acc1);                    \
    }

    const int P = cnt >> 1;           // full pairs
    if (P > 0) {
        // Prologue: fetch pair 0 (steps 0,1)
        int    ia = irow[0], ib = irow[1];
        float  xa = xrow[0], xb = xrow[1];
        float4 Aa0 = __ldg(tA0 + ia * NIO), Aa1 = __ldg(tA1 + ia * NIO);
        float4 Ab0 = __ldg(tA0 + ib * NIO), Ab1 = __ldg(tA1 + ib * NIO);

        for (int kp = 1; kp < P; kp++) {
            // FETCH next pair
            int    na  = irow[2 * kp],     nb2 = irow[2 * kp + 1];
            float  nxa = xrow[2 * kp],     nxb = xrow[2 * kp + 1];
            float4 nAa0 = __ldg(tA0 + na * NIO),  nAa1 = __ldg(tA1 + na * NIO);
            float4 nAb0 = __ldg(tA0 + nb2 * NIO), nAb1 = __ldg(tA1 + nb2 * NIO);

            // COMPUTE current pair: 4 interleaved MUFU chains
            STEP2(ia, xa, Aa0, Aa1);
            STEP2(ib, xb, Ab0, Ab1);

            // rotate
            ia = na;  xa = nxa; Aa0 = nAa0; Aa1 = nAa1;
            ib = nb2; xb = nxb; Ab0 = nAb0; Ab1 = nAb1;
        }
        // Epilogue pair
        STEP2(ia, xa, Aa0, Aa1);
        STEP2(ib, xb, Ab0, Ab1);
    }
    if (cnt & 1) {                    // odd leftover step
        int    ii = irow[cnt - 1];
        float  xv = xrow[cnt - 1];
        float4 A0 = __ldg(tA0 + ii * NIO);
        float4 A1 = __ldg(tA1 + ii * NIO);
        STEP2(ii, xv, A0, A1);
    }
#undef STEP2

    out[base + r * 64 + o]      = acc0;
    out[base + r * 64 + o + 32] = acc1;
}

// ---------------------------------------------------------------------------
extern "C" void kernel_launch(void* const* d_in, const int* in_sizes, int n_in,
                              void* d_out, int out_size)
{
    const float* x   = (const float*)d_in[0];
    const float* rg  = (const float*)d_in[1];
    const float* w   = (const float*)d_in[2];
    const float* br  = (const float*)d_in[3];
    const float* cf  = (const float*)d_in[4];
    const float* mu  = (const float*)d_in[5];
    const float* sg  = (const float*)d_in[6];
    float* out = (float*)d_out;

    setup_kernel<<<(NIO * NIO + 255) / 256, 256>>>(rg, w, br, cf, mu, sg);

    // Main kernel with Programmatic Dependent Launch: its phase 1 overlaps
    // setup_kernel; griddepcontrol.wait gates the table reads.
    cudaLaunchConfig_t cfg = {};
    cfg.gridDim  = dim3(NB / TILE_B);
    cfg.blockDim = dim3(THREADS);
    cfg.dynamicSmemBytes = 0;
    cfg.stream = 0;
    cudaLaunchAttribute attrs[1];
    attrs[0].id = cudaLaunchAttributeProgrammaticStreamSerialization;
    attrs[0].val.programmaticStreamSerializationAllowed = 1;
    cfg.attrs = attrs;
    cfg.numAttrs = 1;
    cudaLaunchKernelEx(&cfg, main_kernel, x, (float*)out);
}